// round 5
// baseline (speedup 1.0000x reference)
#include <cuda_runtime.h>

#define B_   4
#define C_   256
#define CR_  64
#define H_   64
#define W_   64
#define HW_  4096
#define KK_  49
#define G_   16
#define GC_  16
#define OT_  784    // K*K*GROUPS

typedef unsigned long long u64;

// scratch
__device__ float g_x[B_ * CR_ * HW_];          // 4 MB
__device__ float g_w[B_ * OT_ * HW_];          // 51.4 MB dynamic weights

// ---------------- packed f32x2 helpers ----------------
__device__ __forceinline__ u64 pk2(float lo, float hi) {
    u64 r; asm("mov.b64 %0, {%1,%2};" : "=l"(r) : "f"(lo), "f"(hi)); return r;
}
__device__ __forceinline__ void upk2(u64 v, float& lo, float& hi) {
    asm("mov.b64 {%0,%1}, %2;" : "=f"(lo), "=f"(hi) : "l"(v));
}
__device__ __forceinline__ void fma2(u64& d, u64 a, u64 b) {
    asm("fma.rn.f32x2 %0, %1, %2, %0;" : "+l"(d) : "l"(a), "l"(b));
}

// ---------------------------------------------------------------------------
// Kernel 1 (validated, ~12us): x = relu(bn(w1 @ guide))
// ---------------------------------------------------------------------------
__global__ __launch_bounds__(256) void k1_compute_x(
    const float* __restrict__ guide,
    const float* __restrict__ w1,
    const float* __restrict__ gamma,
    const float* __restrict__ beta,
    const float* __restrict__ mean,
    const float* __restrict__ var)
{
    __shared__ float inv_s[CR_];
    __shared__ float bias_s[CR_];
    __shared__ float gtile[16][128];
    __shared__ u64   w1t2[16 * CR_];

    const int t    = threadIdx.x;
    const int b    = blockIdx.y;
    const int pix0 = blockIdx.x * 128;

    if (t < CR_) {
        float iv  = gamma[t] * rsqrtf(var[t] + 1e-5f);
        inv_s[t]  = iv;
        bias_s[t] = beta[t] - mean[t] * iv;
    }
    __syncthreads();

    const int L  = t & 31;
    const int rg = t >> 5;

    u64 acc0[8], acc1[8];
    #pragma unroll
    for (int j = 0; j < 8; j++) { acc0[j] = 0ull; acc1[j] = 0ull; }

    for (int c0 = 0; c0 < C_; c0 += 16) {
        #pragma unroll
        for (int j = 0; j < 8; j++) {
            int idx = t + 256 * j;
            int cc = idx >> 7, px = idx & 127;
            gtile[cc][px] = guide[(b * C_ + c0 + cc) * HW_ + pix0 + px];
        }
        #pragma unroll
        for (int j = 0; j < 4; j++) {
            int idx = t + 256 * j;
            int cc = idx & 15, r = idx >> 4;
            float v = w1[r * C_ + c0 + cc] * inv_s[r];
            w1t2[cc * CR_ + r] = pk2(v, v);
        }
        __syncthreads();

        #pragma unroll 4
        for (int cc = 0; cc < 16; cc++) {
            u64 g0 = *(const u64*)&gtile[cc][2 * L];
            u64 g1 = *(const u64*)&gtile[cc][64 + 2 * L];
            const u64* wp = &w1t2[cc * CR_ + rg * 8];
            #pragma unroll
            for (int rr = 0; rr < 8; rr++) {
                u64 wv = wp[rr];
                fma2(acc0[rr], wv, g0);
                fma2(acc1[rr], wv, g1);
            }
        }
        __syncthreads();
    }

    #pragma unroll
    for (int rr = 0; rr < 8; rr++) {
        int r = rg * 8 + rr;
        float bb = bias_s[r];
        float a, c, d, e;
        upk2(acc0[rr], a, c);
        upk2(acc1[rr], d, e);
        float2 v0 = make_float2(fmaxf(a + bb, 0.f), fmaxf(c + bb, 0.f));
        float2 v1 = make_float2(fmaxf(d + bb, 0.f), fmaxf(e + bb, 0.f));
        float* dst = &g_x[(b * CR_ + r) * HW_ + pix0];
        *(float2*)&dst[2 * L]      = v0;
        *(float2*)&dst[64 + 2 * L] = v1;
    }
}

// ---------------------------------------------------------------------------
// Kernel 2': weight GEMM  g_w[b][o][px] = w2[o,:] . x[b,:,px] + b2[o]
// Tile 112 o x 128 px, K = 64. 256 threads: 16 og(7 o) x 16 pg(8 px).
// grid (7, 32, B)
// ---------------------------------------------------------------------------
#define WS_U64   (64 * 113)                 // [r][o] dup pairs, pad 113
#define XS_OFF   (WS_U64 * 2)               // float idx of xs[64][128]
#define B2S_OFF  (XS_OFF + 64 * 128)
#define SMEMW_FLOATS (B2S_OFF + 112)
#define SMEMW_BYTES  (SMEMW_FLOATS * 4)

__global__ __launch_bounds__(256, 2) void k2_wgemm(
    const float* __restrict__ w2,
    const float* __restrict__ b2)
{
    extern __shared__ float smw[];
    u64*   ws  = (u64*)smw;
    float* xs  = smw + XS_OFF;
    float* b2s = smw + B2S_OFF;

    const int t   = threadIdx.x;
    const int o0  = blockIdx.x * 112;
    const int px0 = blockIdx.y * 128;
    const int b   = blockIdx.z;

    // load x tile [64 r][128 px] via float4
    {
        const float4* src = (const float4*)&g_x[b * CR_ * HW_ + px0];
        #pragma unroll
        for (int j = 0; j < 8; j++) {
            int idx = t + 256 * j;            // 2048 float4
            int r = idx >> 5, c4 = idx & 31;
            *(float4*)&xs[r * 128 + c4 * 4] = src[r * (HW_ / 4) + c4];
        }
    }
    // load w2 slice transposed + duplicated: ws[r*113 + o] = {w,w}
    #pragma unroll
    for (int j = 0; j < 28; j++) {
        int idx = t + 256 * j;                 // 7168 = 112*64
        int o = idx >> 6, r = idx & 63;
        float v = w2[(o0 + o) * CR_ + r];      // coalesced over r
        ws[r * 113 + o] = pk2(v, v);
    }
    if (t < 112) b2s[t] = b2[o0 + t];
    __syncthreads();

    const int og = t >> 4;       // 0..15 -> o = og*7 .. og*7+6
    const int pg = t & 15;       // 0..15 -> px = pg*8 .. pg*8+7

    u64 acc[7][4];
    #pragma unroll
    for (int i = 0; i < 7; i++)
        #pragma unroll
        for (int j = 0; j < 4; j++) acc[i][j] = 0ull;

    const int ob = og * 7;
    #pragma unroll 2
    for (int r = 0; r < CR_; r++) {
        ulonglong2 xa = *(const ulonglong2*)&xs[r * 128 + pg * 8];
        ulonglong2 xb = *(const ulonglong2*)&xs[r * 128 + pg * 8 + 4];
        const u64* wr = &ws[r * 113 + ob];
        #pragma unroll
        for (int oo = 0; oo < 7; oo++) {
            u64 w = wr[oo];                    // broadcast LDS.64
            fma2(acc[oo][0], w, xa.x);
            fma2(acc[oo][1], w, xa.y);
            fma2(acc[oo][2], w, xb.x);
            fma2(acc[oo][3], w, xb.y);
        }
    }

    // epilogue: add bias, store float4 x2 per o
    #pragma unroll
    for (int oo = 0; oo < 7; oo++) {
        float bv = b2s[ob + oo];
        float l0, h0, l1, h1, l2, h2, l3, h3;
        upk2(acc[oo][0], l0, h0); upk2(acc[oo][1], l1, h1);
        upk2(acc[oo][2], l2, h2); upk2(acc[oo][3], l3, h3);
        float* dst = &g_w[(b * OT_ + o0 + ob + oo) * HW_ + px0 + pg * 8];
        *(float4*)dst       = make_float4(l0 + bv, h0 + bv, l1 + bv, h1 + bv);
        *(float4*)(dst + 4) = make_float4(l2 + bv, h2 + bv, l3 + bv, h3 + bv);
    }
}

// ---------------------------------------------------------------------------
// Kernel 3: aggregation + residual.
// Block = 2 image rows (128 px) x 2 groups. grid (32 y2, B, 8 gh).
// Threads 256: pxq = t&63 (pixel pair), chq = t>>6 (4 channels).
// Weights streamed from g_w via LDG.64 (L1 reuse x4).
// ---------------------------------------------------------------------------
__global__ __launch_bounds__(256) void k3_aggregate(
    const float* __restrict__ feat,
    float* __restrict__ out)
{
    __shared__ float fh[16 * 8 * 72];        // [c][iy 0..7][72]

    const int t   = threadIdx.x;
    const int y0  = blockIdx.x * 2;
    const int b   = blockIdx.y;
    const int gh  = blockIdx.z;              // groups 2*gh, 2*gh+1

    const int pxq = t & 63;                  // pixel pair p = 2*pxq (0..126)
    const int chq = t >> 6;                  // channels 4*chq .. +3
    const int p   = 2 * pxq;
    const int ry  = p >> 6;                  // 0 or 1
    const int cx  = p & 63;                  // even

    for (int gi = 0; gi < 2; gi++) {
        const int g = gh * 2 + gi;

        // ---- halo: 16 ch x 8 rows x 70 cols (stride 72), zero-pad ----
        #pragma unroll
        for (int j = 0; j < 35; j++) {
            int idx = t + 256 * j;
            if (idx < 16 * 560) {
                int cc  = idx / 560;
                int rem = idx - cc * 560;
                int iy  = rem / 70;
                int ix  = rem - iy * 70;
                int gy = y0 + iy - 3, gx = ix - 3;
                float v = 0.f;
                if ((unsigned)gy < 64u && (unsigned)gx < 64u)
                    v = feat[(b * C_ + g * GC_ + cc) * HW_ + gy * W_ + gx];
                fh[cc * 576 + iy * 72 + ix] = v;
            }
        }
        __syncthreads();

        float oacc[2][4] = {{0.f,0.f,0.f,0.f},{0.f,0.f,0.f,0.f}};

        const float* wbase =
            &g_w[(b * OT_ + g * KK_) * HW_ + y0 * W_ + p];

        #pragma unroll
        for (int ky = 0; ky < 7; ky++) {
            float wk0[7], wk1[7];
            #pragma unroll
            for (int kx = 0; kx < 7; kx++) {
                u64 wv = *(const u64*)(wbase + (ky * 7 + kx) * HW_);
                upk2(wv, wk0[kx], wk1[kx]);
            }
            #pragma unroll
            for (int c = 0; c < 4; c++) {
                const float* frow =
                    &fh[(chq * 4 + c) * 576 + (ry + ky) * 72 + cx];
                float2 f0 = *(const float2*)(frow);
                float2 f1 = *(const float2*)(frow + 2);
                float2 f2 = *(const float2*)(frow + 4);
                float2 f3 = *(const float2*)(frow + 6);
                float e[8] = {f0.x, f0.y, f1.x, f1.y,
                              f2.x, f2.y, f3.x, f3.y};
                #pragma unroll
                for (int kx = 0; kx < 7; kx++) {
                    oacc[0][c] += wk0[kx] * e[kx];
                    oacc[1][c] += wk1[kx] * e[kx + 1];
                }
            }
        }

        // residual + store
        #pragma unroll
        for (int c = 0; c < 4; c++) {
            int cc = chq * 4 + c;
            int ch = g * GC_ + cc;
            float r0 = fh[cc * 576 + (ry + 3) * 72 + cx + 3];
            float r1 = fh[cc * 576 + (ry + 3) * 72 + cx + 4];
            *(float2*)&out[(b * C_ + ch) * HW_ + (y0 + ry) * W_ + cx] =
                make_float2(oacc[0][c] + r0, oacc[1][c] + r1);
        }
        __syncthreads();   // before halo overwrite
    }
}

// ---------------------------------------------------------------------------
extern "C" void kernel_launch(void* const* d_in, const int* in_sizes, int n_in,
                              void* d_out, int out_size)
{
    const float* feat  = (const float*)d_in[0];
    const float* guide = (const float*)d_in[1];
    const float* w1    = (const float*)d_in[2];
    const float* gamma = (const float*)d_in[3];
    const float* beta  = (const float*)d_in[4];
    const float* mean  = (const float*)d_in[5];
    const float* var   = (const float*)d_in[6];
    const float* w2    = (const float*)d_in[7];
    const float* b2    = (const float*)d_in[8];
    float* out = (float*)d_out;

    cudaFuncSetAttribute(k2_wgemm,
                         cudaFuncAttributeMaxDynamicSharedMemorySize,
                         SMEMW_BYTES);

    k1_compute_x<<<dim3(32, B_), 256>>>(guide, w1, gamma, beta, mean, var);
    k2_wgemm<<<dim3(7, 32, B_), 256, SMEMW_BYTES>>>(w2, b2);
    k3_aggregate<<<dim3(32, B_, 8), 256>>>(feat, out);
}

// round 6
// speedup vs baseline: 1.0186x; 1.0186x over previous
#include <cuda_runtime.h>

#define B_   4
#define C_   256
#define CR_  64
#define H_   64
#define W_   64
#define HW_  4096
#define KK_  49
#define G_   16
#define GC_  16
#define OT_  784    // K*K*GROUPS

typedef unsigned long long u64;

// scratch
__device__ float g_x[B_ * CR_ * HW_];          // 4 MB
__device__ float g_w[B_ * OT_ * HW_];          // 51.4 MB dynamic weights

// ---------------- packed f32x2 helpers ----------------
__device__ __forceinline__ u64 pk2(float lo, float hi) {
    u64 r; asm("mov.b64 %0, {%1,%2};" : "=l"(r) : "f"(lo), "f"(hi)); return r;
}
__device__ __forceinline__ void upk2(u64 v, float& lo, float& hi) {
    asm("mov.b64 {%0,%1}, %2;" : "=f"(lo), "=f"(hi) : "l"(v));
}
__device__ __forceinline__ void fma2(u64& d, u64 a, u64 b) {
    asm("fma.rn.f32x2 %0, %1, %2, %0;" : "+l"(d) : "l"(a), "l"(b));
}

// ---------------------------------------------------------------------------
// Kernel 1: x = relu(bn(w1 @ guide)).  512 thr: 32 px-pair lanes x 16 r-groups
// of 4 r.  grid (32, B).  Weight LDS are full-warp broadcasts.
// ---------------------------------------------------------------------------
__global__ __launch_bounds__(512) void k1_compute_x(
    const float* __restrict__ guide,
    const float* __restrict__ w1,
    const float* __restrict__ gamma,
    const float* __restrict__ beta,
    const float* __restrict__ mean,
    const float* __restrict__ var)
{
    __shared__ float inv_s[CR_];
    __shared__ float bias_s[CR_];
    __shared__ float gtile[16][128];
    __shared__ u64   w1t2[16 * CR_];

    const int t    = threadIdx.x;
    const int b    = blockIdx.y;
    const int pix0 = blockIdx.x * 128;

    if (t < CR_) {
        float iv  = gamma[t] * rsqrtf(var[t] + 1e-5f);
        inv_s[t]  = iv;
        bias_s[t] = beta[t] - mean[t] * iv;
    }
    __syncthreads();

    const int L  = t & 31;      // pixel pair lane: pairs {2L, 2L+1}, {64+2L,..}
    const int rg = t >> 5;      // warp id = r-group: 4 r values

    u64 acc0[4], acc1[4];
    #pragma unroll
    for (int j = 0; j < 4; j++) { acc0[j] = 0ull; acc1[j] = 0ull; }

    for (int c0 = 0; c0 < C_; c0 += 16) {
        #pragma unroll
        for (int j = 0; j < 4; j++) {           // guide tile 16x128
            int idx = t + 512 * j;
            int cc = idx >> 7, px = idx & 127;
            gtile[cc][px] = guide[(b * C_ + c0 + cc) * HW_ + pix0 + px];
        }
        #pragma unroll
        for (int j = 0; j < 2; j++) {           // w1 tile, BN-folded, dup pairs
            int idx = t + 512 * j;
            int cc = idx & 15, r = idx >> 4;
            float v = w1[r * C_ + c0 + cc] * inv_s[r];
            w1t2[cc * CR_ + r] = pk2(v, v);
        }
        __syncthreads();

        #pragma unroll 4
        for (int cc = 0; cc < 16; cc++) {
            u64 g0 = *(const u64*)&gtile[cc][2 * L];
            u64 g1 = *(const u64*)&gtile[cc][64 + 2 * L];
            // 4 weights for this warp's r-group: two LDS.128 broadcasts
            ulonglong2 wab = *(const ulonglong2*)&w1t2[cc * CR_ + rg * 4];
            ulonglong2 wcd = *(const ulonglong2*)&w1t2[cc * CR_ + rg * 4 + 2];
            fma2(acc0[0], wab.x, g0); fma2(acc1[0], wab.x, g1);
            fma2(acc0[1], wab.y, g0); fma2(acc1[1], wab.y, g1);
            fma2(acc0[2], wcd.x, g0); fma2(acc1[2], wcd.x, g1);
            fma2(acc0[3], wcd.y, g0); fma2(acc1[3], wcd.y, g1);
        }
        __syncthreads();
    }

    #pragma unroll
    for (int rr = 0; rr < 4; rr++) {
        int r = rg * 4 + rr;
        float bb = bias_s[r];
        float a, c, d, e;
        upk2(acc0[rr], a, c);
        upk2(acc1[rr], d, e);
        float2 v0 = make_float2(fmaxf(a + bb, 0.f), fmaxf(c + bb, 0.f));
        float2 v1 = make_float2(fmaxf(d + bb, 0.f), fmaxf(e + bb, 0.f));
        float* dst = &g_x[(b * CR_ + r) * HW_ + pix0];
        *(float2*)&dst[2 * L]      = v0;
        *(float2*)&dst[64 + 2 * L] = v1;
    }
}

// ---------------------------------------------------------------------------
// Kernel 2': weight GEMM  g_w[b][o][px] = w2[o,:] . x[b,:,px] + b2[o]
// Tile 112 o x 128 px, K = 64. 512 threads: 16 og(7 o) x 32 pg(4 px).
// 14 u64 accs (28 regs) -> no spill.  grid (7, 32, B)
// ---------------------------------------------------------------------------
#define WS_U64   (64 * 113)                 // [r][o] dup pairs, pad 113
#define XS_OFF   (WS_U64 * 2)               // float idx of xs[64][128]
#define B2S_OFF  (XS_OFF + 64 * 128)
#define SMEMW_FLOATS (B2S_OFF + 112)
#define SMEMW_BYTES  (SMEMW_FLOATS * 4)

__global__ __launch_bounds__(512) void k2_wgemm(
    const float* __restrict__ w2,
    const float* __restrict__ b2)
{
    extern __shared__ float smw[];
    u64*   ws  = (u64*)smw;
    float* xs  = smw + XS_OFF;
    float* b2s = smw + B2S_OFF;

    const int t   = threadIdx.x;
    const int o0  = blockIdx.x * 112;
    const int px0 = blockIdx.y * 128;
    const int b   = blockIdx.z;

    // load x tile [64 r][128 px] via float4
    {
        const float4* src = (const float4*)&g_x[b * CR_ * HW_ + px0];
        #pragma unroll
        for (int j = 0; j < 4; j++) {
            int idx = t + 512 * j;            // 2048 float4
            int r = idx >> 5, c4 = idx & 31;
            *(float4*)&xs[r * 128 + c4 * 4] = src[r * (HW_ / 4) + c4];
        }
    }
    // load w2 slice transposed + duplicated: ws[r*113 + o] = {w,w}
    #pragma unroll
    for (int j = 0; j < 14; j++) {
        int idx = t + 512 * j;                 // 7168 = 112*64
        int o = idx >> 6, r = idx & 63;
        ws[r * 113 + o] = pk2(w2[(o0 + o) * CR_ + r], w2[(o0 + o) * CR_ + r]);
    }
    if (t < 112) b2s[t] = b2[o0 + t];
    __syncthreads();

    const int og = t >> 5;       // warp id: o = og*7 .. og*7+6  (broadcast w)
    const int pg = t & 31;       // px = pg*4 .. pg*4+3

    u64 acc[7][2];
    #pragma unroll
    for (int i = 0; i < 7; i++) { acc[i][0] = 0ull; acc[i][1] = 0ull; }

    const int ob = og * 7;
    #pragma unroll 2
    for (int r = 0; r < CR_; r++) {
        ulonglong2 xa = *(const ulonglong2*)&xs[r * 128 + pg * 4];
        const u64* wr = &ws[r * 113 + ob];
        #pragma unroll
        for (int oo = 0; oo < 7; oo++) {
            u64 w = wr[oo];                    // full-warp broadcast LDS.64
            fma2(acc[oo][0], w, xa.x);
            fma2(acc[oo][1], w, xa.y);
        }
    }

    // epilogue: add bias, store one float4 per o
    #pragma unroll
    for (int oo = 0; oo < 7; oo++) {
        float bv = b2s[ob + oo];
        float l0, h0, l1, h1;
        upk2(acc[oo][0], l0, h0);
        upk2(acc[oo][1], l1, h1);
        *(float4*)&g_w[(b * OT_ + o0 + ob + oo) * HW_ + px0 + pg * 4] =
            make_float4(l0 + bv, h0 + bv, l1 + bv, h1 + bv);
    }
}

// ---------------------------------------------------------------------------
// Kernel 3: aggregation + residual (unchanged from R5).
// Block = 2 image rows x 2 groups. grid (32, B, 8). 256 thr.
// ---------------------------------------------------------------------------
__global__ __launch_bounds__(256) void k3_aggregate(
    const float* __restrict__ feat,
    float* __restrict__ out)
{
    __shared__ float fh[16 * 8 * 72];        // [c][iy 0..7][72]

    const int t   = threadIdx.x;
    const int y0  = blockIdx.x * 2;
    const int b   = blockIdx.y;
    const int gh  = blockIdx.z;

    const int pxq = t & 63;
    const int chq = t >> 6;
    const int p   = 2 * pxq;
    const int ry  = p >> 6;
    const int cx  = p & 63;

    for (int gi = 0; gi < 2; gi++) {
        const int g = gh * 2 + gi;

        #pragma unroll
        for (int j = 0; j < 35; j++) {
            int idx = t + 256 * j;
            if (idx < 16 * 560) {
                int cc  = idx / 560;
                int rem = idx - cc * 560;
                int iy  = rem / 70;
                int ix  = rem - iy * 70;
                int gy = y0 + iy - 3, gx = ix - 3;
                float v = 0.f;
                if ((unsigned)gy < 64u && (unsigned)gx < 64u)
                    v = feat[(b * C_ + g * GC_ + cc) * HW_ + gy * W_ + gx];
                fh[cc * 576 + iy * 72 + ix] = v;
            }
        }
        __syncthreads();

        float oacc[2][4] = {{0.f,0.f,0.f,0.f},{0.f,0.f,0.f,0.f}};

        const float* wbase =
            &g_w[(b * OT_ + g * KK_) * HW_ + y0 * W_ + p];

        #pragma unroll
        for (int ky = 0; ky < 7; ky++) {
            float wk0[7], wk1[7];
            #pragma unroll
            for (int kx = 0; kx < 7; kx++) {
                u64 wv = *(const u64*)(wbase + (ky * 7 + kx) * HW_);
                upk2(wv, wk0[kx], wk1[kx]);
            }
            #pragma unroll
            for (int c = 0; c < 4; c++) {
                const float* frow =
                    &fh[(chq * 4 + c) * 576 + (ry + ky) * 72 + cx];
                float2 f0 = *(const float2*)(frow);
                float2 f1 = *(const float2*)(frow + 2);
                float2 f2 = *(const float2*)(frow + 4);
                float2 f3 = *(const float2*)(frow + 6);
                float e[8] = {f0.x, f0.y, f1.x, f1.y,
                              f2.x, f2.y, f3.x, f3.y};
                #pragma unroll
                for (int kx = 0; kx < 7; kx++) {
                    oacc[0][c] += wk0[kx] * e[kx];
                    oacc[1][c] += wk1[kx] * e[kx + 1];
                }
            }
        }

        #pragma unroll
        for (int c = 0; c < 4; c++) {
            int cc = chq * 4 + c;
            int ch = g * GC_ + cc;
            float r0 = fh[cc * 576 + (ry + 3) * 72 + cx + 3];
            float r1 = fh[cc * 576 + (ry + 3) * 72 + cx + 4];
            *(float2*)&out[(b * C_ + ch) * HW_ + (y0 + ry) * W_ + cx] =
                make_float2(oacc[0][c] + r0, oacc[1][c] + r1);
        }
        __syncthreads();
    }
}

// ---------------------------------------------------------------------------
extern "C" void kernel_launch(void* const* d_in, const int* in_sizes, int n_in,
                              void* d_out, int out_size)
{
    const float* feat  = (const float*)d_in[0];
    const float* guide = (const float*)d_in[1];
    const float* w1    = (const float*)d_in[2];
    const float* gamma = (const float*)d_in[3];
    const float* beta  = (const float*)d_in[4];
    const float* mean  = (const float*)d_in[5];
    const float* var   = (const float*)d_in[6];
    const float* w2    = (const float*)d_in[7];
    const float* b2    = (const float*)d_in[8];
    float* out = (float*)d_out;

    cudaFuncSetAttribute(k2_wgemm,
                         cudaFuncAttributeMaxDynamicSharedMemorySize,
                         SMEMW_BYTES);

    k1_compute_x<<<dim3(32, B_), 512>>>(guide, w1, gamma, beta, mean, var);
    k2_wgemm<<<dim3(7, 32, B_), 512, SMEMW_BYTES>>>(w2, b2);
    k3_aggregate<<<dim3(32, B_, 8), 256>>>(feat, out);
}